// round 2
// baseline (speedup 1.0000x reference)
#include <cuda_runtime.h>
#include <math.h>

#define NTASK   2000
#define NSUP    25
#define NQ      75
#define DIM     640
#define KW      5            // n_ways
#define NLAYERS 20
#define R       80           // extended rows: 75 query + 5 class-sum rows
#define DC      64           // d-chunk width
#define NCHUNK  (DIM / DC)
#define PADC    68           // chunk row stride (floats): 16B-aligned rows, bank-shifted
#define PADG    81           // Gram row stride (odd -> conflict-free column walks)
#define PADU    8            // U/GU row stride (float4-friendly)
#define EPS     1e-6f

__global__ __launch_bounds__(256, 2)
void fewshot_kernel(const float* __restrict__ Zs_g,
                    const int*   __restrict__ Y_g,
                    const float* __restrict__ Zq_g,
                    const float* __restrict__ t1_p,
                    const float* __restrict__ gm_p,
                    const float* __restrict__ t2_p,
                    float*       __restrict__ out)
{
    // ---- shared memory (aliased across phases to stay < 48KB static) ----
    __shared__ __align__(16) float Zx[R * PADC];   // 21760 B; later hosts U_s / GU_s
    __shared__ __align__(16) float G [R * PADG];   // 25920 B; hosts support staging during chunks
    __shared__ float invden_s[KW], halfnn_s[KW], gV_s[KW], ssq_s[KW], cnt_s[KW];
    __shared__ int   Y_sh[NSUP];

    float* Sup  = G;                 // support staging (1700 floats) lives in G before G is written
    float* U_s  = Zx;                // [NQ][PADU]
    float* GU_s = Zx + NQ * PADU;    // [NQ][PADU]

    const int b = blockIdx.x;
    const int t = threadIdx.x;

    const float c      = log1pf(expf(t1_p[0]));          // softplus(t1)
    const float g      = log1pf(expf(gm_p[0]));          // softplus(gamma)
    const float inv_t2 = 1.0f / (log1pf(expf(t2_p[0])) + 1.0f);

    if (t < NSUP) Y_sh[t] = Y_g[b * NSUP + t];
    __syncthreads();

    // ---- Phase 1: extended Gram Gx = Zx Zx^T, Zx = [c*Zq ; c*class_sums] ----
    // 16x16 grid of 5x5 register tiles -> exactly 256 threads, one tile each.
    const int ti = t >> 4, tj = t & 15;
    const int ri = ti * 5, rj = tj * 5;

    unsigned long long acc[25];
    #pragma unroll
    for (int i = 0; i < 25; i++) acc[i] = 0ull;

    const float* Zq_b = Zq_g + (size_t)b * NQ   * DIM;
    const float* Zs_b = Zs_g + (size_t)b * NSUP * DIM;

    for (int ch = 0; ch < NCHUNK; ch++) {
        const int d0 = ch * DC;
        // stage query rows (scaled)
        for (int idx = t; idx < NQ * (DC / 4); idx += 256) {
            const int q = idx / (DC / 4);
            const int v = idx % (DC / 4);
            float4 x = *(const float4*)(Zq_b + q * DIM + d0 + 4 * v);
            float* dst = &Zx[q * PADC + 4 * v];
            dst[0] = c * x.x; dst[1] = c * x.y; dst[2] = c * x.z; dst[3] = c * x.w;
        }
        // stage raw support rows
        for (int idx = t; idx < NSUP * (DC / 4); idx += 256) {
            const int s = idx / (DC / 4);
            const int v = idx % (DC / 4);
            float4 x = *(const float4*)(Zs_b + s * DIM + d0 + 4 * v);
            float* dst = &Sup[s * PADC + 4 * v];
            dst[0] = x.x; dst[1] = x.y; dst[2] = x.z; dst[3] = x.w;
        }
        __syncthreads();
        // class sums -> rows 75..79 (scaled)
        for (int idx = t; idx < KW * DC; idx += 256) {
            const int dl = idx & (DC - 1);
            const int k  = idx >> 6;
            float s = 0.f;
            #pragma unroll
            for (int j = 0; j < NSUP; j++)
                if (Y_sh[j] == k) s += Sup[j * PADC + dl];
            Zx[(NQ + k) * PADC + dl] = c * s;
        }
        __syncthreads();
        // accumulate 5x5 tile with packed f32x2 FMA (2 d at a time)
        for (int dl = 0; dl < DC; dl += 2) {
            unsigned long long av[5], bv[5];
            #pragma unroll
            for (int i = 0; i < 5; i++) {
                av[i] = *(const unsigned long long*)&Zx[(ri + i) * PADC + dl];
                bv[i] = *(const unsigned long long*)&Zx[(rj + i) * PADC + dl];
            }
            #pragma unroll
            for (int i = 0; i < 5; i++)
                #pragma unroll
                for (int j = 0; j < 5; j++)
                    asm("fma.rn.f32x2 %0, %1, %2, %0;"
                        : "+l"(acc[i * 5 + j]) : "l"(av[i]), "l"(bv[j]));
        }
        __syncthreads();
    }

    // finalize Gram: lo+hi halves of packed accumulators
    #pragma unroll
    for (int i = 0; i < 5; i++)
        #pragma unroll
        for (int j = 0; j < 5; j++) {
            const unsigned long long x = acc[i * 5 + j];
            const float lo = __uint_as_float((unsigned)(x & 0xffffffffu));
            const float hi = __uint_as_float((unsigned)(x >> 32));
            G[(ri + i) * PADG + (rj + j)] = lo + hi;
        }
    __syncthreads();

    // ---- init per-class iteration state ----
    if (t < KW) {
        const int k = t;
        float cn = 0.f;
        #pragma unroll
        for (int j = 0; j < NSUP; j++) cn += (Y_sh[j] == k) ? 1.f : 0.f;
        const float ssq = G[(NQ + k) * PADG + (NQ + k)];
        const float iv  = 1.0f / cn;
        cnt_s[k]    = cn;
        ssq_s[k]    = ssq;
        invden_s[k] = iv;
        halfnn_s[k] = 0.5f * ssq * iv * iv;
        gV_s[k]     = g;                       // V0 = 1
    }
    __syncthreads();

    // per-thread constants for the loop (S column for this q is constant)
    const int q = t;
    float sk[KW], gu[KW];
    #pragma unroll
    for (int k = 0; k < KW; k++) gu[k] = 0.f;
    if (q < NQ) {
        #pragma unroll
        for (int k = 0; k < KW; k++) sk[k] = G[(NQ + k) * PADG + q];
    }

    // ---- Phase 2: 20 fixed-point layers, all in SMEM/registers ----
    for (int it = 0; it < NLAYERS; it++) {
        float u[KW];
        if (q < NQ) {
            float a[KW], m = -1e30f;
            #pragma unroll
            for (int k = 0; k < KW; k++) {
                a[k] = inv_t2 * ((gu[k] + sk[k]) * invden_s[k] - halfnn_s[k] + gV_s[k]);
                m = fmaxf(m, a[k]);
            }
            float ssum = 0.f;
            #pragma unroll
            for (int k = 0; k < KW; k++) { u[k] = __expf(a[k] - m); ssum += u[k]; }
            const float r = 1.0f / ssum;
            #pragma unroll
            for (int k = 0; k < KW; k++) u[k] *= r;

            if (it == NLAYERS - 1) {
                float* o = out + ((size_t)b * NQ + q) * KW;
                #pragma unroll
                for (int k = 0; k < KW; k++) o[k] = u[k];
            } else {
                #pragma unroll
                for (int k = 0; k < KW; k++) U_s[q * PADU + k] = u[k];
            }
        }
        if (it == NLAYERS - 1) break;
        __syncthreads();

        // GU = G[0:75,0:75] @ U   (thread-per-q, 5 accumulators)
        if (q < NQ) {
            float ng0 = 0.f, ng1 = 0.f, ng2 = 0.f, ng3 = 0.f, ng4 = 0.f;
            const float* Grow = &G[q * PADG];
            for (int qp = 0; qp < NQ; qp++) {
                const float gv = Grow[qp];
                const float4 u4 = *(const float4*)&U_s[qp * PADU];
                const float  u5 = U_s[qp * PADU + 4];
                ng0 += gv * u4.x; ng1 += gv * u4.y; ng2 += gv * u4.z;
                ng3 += gv * u4.w; ng4 += gv * u5;
            }
            gu[0] = ng0; gu[1] = ng1; gu[2] = ng2; gu[3] = ng3; gu[4] = ng4;
            GU_s[q * PADU + 0] = ng0; GU_s[q * PADU + 1] = ng1;
            GU_s[q * PADU + 2] = ng2; GU_s[q * PADU + 3] = ng3;
            GU_s[q * PADU + 4] = ng4;
        }
        __syncthreads();

        // per-class reductions: warp w handles class w
        const int w = t >> 5, lane = t & 31;
        if (w < KW) {
            const int k = w;
            float usum = 0.f, ups = 0.f, ugu = 0.f;
            for (int qq = lane; qq < NQ; qq += 32) {
                const float uv = U_s[qq * PADU + k];
                usum += uv;
                ups  += uv * G[(NQ + k) * PADG + qq];
                ugu  += uv * GU_s[qq * PADU + k];
            }
            #pragma unroll
            for (int o = 16; o > 0; o >>= 1) {
                usum += __shfl_down_sync(0xffffffffu, usum, o);
                ups  += __shfl_down_sync(0xffffffffu, ups,  o);
                ugu  += __shfl_down_sync(0xffffffffu, ugu,  o);
            }
            if (lane == 0) {
                const float den = usum + cnt_s[k];
                const float iv  = 1.0f / den;
                const float nn  = ugu + 2.f * ups + ssq_s[k];
                invden_s[k] = iv;
                halfnn_s[k] = 0.5f * nn * iv * iv;
                gV_s[k]     = g * (logf(usum / (float)NQ + EPS) + 1.0f);
            }
        }
        __syncthreads();
    }
}

extern "C" void kernel_launch(void* const* d_in, const int* in_sizes, int n_in,
                              void* d_out, int out_size)
{
    const float* Zs = (const float*)d_in[0];
    const int*   Y  = (const int*)  d_in[1];
    const float* Zq = (const float*)d_in[2];
    const float* t1 = (const float*)d_in[3];
    const float* gm = (const float*)d_in[4];
    const float* t2 = (const float*)d_in[5];
    fewshot_kernel<<<NTASK, 256>>>(Zs, Y, Zq, t1, gm, t2, (float*)d_out);
}

// round 3
// speedup vs baseline: 1.1234x; 1.1234x over previous
#include <cuda_runtime.h>
#include <math.h>

#define NTASK   2000
#define NSUP    25
#define NQ      75
#define DIM     640
#define KW      5
#define NLAYERS 20
#define R       80
#define DC      64
#define NCHUNK  (DIM / DC)
#define PADC    66           // row stride: 10*PADC=660≡20b mod32 -> conflict-free bv
#define PADG    81
#define PADU    8
#define EPS     1e-6f
#define NTHR    128

__global__ __launch_bounds__(NTHR, 3)
void fewshot_kernel(const float* __restrict__ Zs_g,
                    const int*   __restrict__ Y_g,
                    const float* __restrict__ Zq_g,
                    const float* __restrict__ t1_p,
                    const float* __restrict__ gm_p,
                    const float* __restrict__ t2_p,
                    float*       __restrict__ out)
{
    __shared__ __align__(16) float Zx[R * PADC];   // 21120 B ; later U_s/GU_s
    __shared__ __align__(16) float G [R * PADG];   // 25920 B ; support staging early
    __shared__ float invden_s[KW], halfnn_s[KW], gV_s[KW], ssq_s[KW], cnt_s[KW];
    __shared__ int   Y_sh[NSUP];

    float* Sup  = G;
    float* U_s  = Zx;
    float* GU_s = Zx + NQ * PADU;

    const int b = blockIdx.x;
    const int t = threadIdx.x;

    const float c      = log1pf(expf(t1_p[0]));
    const float g      = log1pf(expf(gm_p[0]));
    const float inv_t2 = 1.0f / (log1pf(expf(t2_p[0])) + 1.0f);

    if (t < NSUP) Y_sh[t] = Y_g[b * NSUP + t];
    __syncthreads();

    // ---- Phase 1: Gram of Zx = [c*Zq ; c*class_sums], 80x80x640 ----
    // 4 warps; lane -> a=lane>>3 (ti sub), b8=lane&7 (tj sub); tile 5x10.
    const int w    = t >> 5;
    const int lane = t & 31;
    const int ri = w * 20 + (lane >> 3) * 5;   // 16 groups of 5 rows
    const int rj = (lane & 7) * 10;            // 8 groups of 10 rows

    unsigned long long acc[50];
    #pragma unroll
    for (int i = 0; i < 50; i++) acc[i] = 0ull;

    const float* Zq_b = Zq_g + (size_t)b * NQ   * DIM;
    const float* Zs_b = Zs_g + (size_t)b * NSUP * DIM;

    for (int ch = 0; ch < NCHUNK; ch++) {
        const int d0 = ch * DC;
        // stage query rows (scaled); float2 stores (rows only 8B-aligned)
        for (int idx = t; idx < NQ * (DC / 4); idx += NTHR) {
            const int q = idx / (DC / 4);
            const int v = idx % (DC / 4);
            float4 x = *(const float4*)(Zq_b + q * DIM + d0 + 4 * v);
            float2* dst = (float2*)&Zx[q * PADC + 4 * v];
            dst[0] = make_float2(c * x.x, c * x.y);
            dst[1] = make_float2(c * x.z, c * x.w);
        }
        // stage raw support rows
        for (int idx = t; idx < NSUP * (DC / 4); idx += NTHR) {
            const int s = idx / (DC / 4);
            const int v = idx % (DC / 4);
            float4 x = *(const float4*)(Zs_b + s * DIM + d0 + 4 * v);
            float2* dst = (float2*)&Sup[s * PADC + 4 * v];
            dst[0] = make_float2(x.x, x.y);
            dst[1] = make_float2(x.z, x.w);
        }
        __syncthreads();
        // class sums -> rows 75..79 (scaled)
        for (int idx = t; idx < KW * DC; idx += NTHR) {
            const int dl = idx & (DC - 1);
            const int k  = idx >> 6;
            float s = 0.f;
            #pragma unroll
            for (int j = 0; j < NSUP; j++)
                if (Y_sh[j] == k) s += Sup[j * PADC + dl];
            Zx[(NQ + k) * PADC + dl] = c * s;
        }
        __syncthreads();

        #pragma unroll 2
        for (int dl = 0; dl < DC; dl += 2) {
            unsigned long long av[5], bv[10];
            #pragma unroll
            for (int i = 0; i < 5; i++)
                av[i] = *(const unsigned long long*)&Zx[(ri + i) * PADC + dl];
            #pragma unroll
            for (int j = 0; j < 10; j++)
                bv[j] = *(const unsigned long long*)&Zx[(rj + j) * PADC + dl];
            #pragma unroll
            for (int i = 0; i < 5; i++)
                #pragma unroll
                for (int j = 0; j < 10; j++)
                    asm("fma.rn.f32x2 %0, %1, %2, %0;"
                        : "+l"(acc[i * 10 + j]) : "l"(av[i]), "l"(bv[j]));
        }
        __syncthreads();
    }

    // finalize: fold packed halves into G
    #pragma unroll
    for (int i = 0; i < 5; i++)
        #pragma unroll
        for (int j = 0; j < 10; j++) {
            const unsigned long long x = acc[i * 10 + j];
            const float lo = __uint_as_float((unsigned)(x & 0xffffffffu));
            const float hi = __uint_as_float((unsigned)(x >> 32));
            G[(ri + i) * PADG + (rj + j)] = lo + hi;
        }
    __syncthreads();

    // ---- init per-class state ----
    if (t < KW) {
        const int k = t;
        float cn = 0.f;
        #pragma unroll
        for (int j = 0; j < NSUP; j++) cn += (Y_sh[j] == k) ? 1.f : 0.f;
        const float ssq = G[(NQ + k) * PADG + (NQ + k)];
        const float iv  = 1.0f / cn;
        cnt_s[k]    = cn;
        ssq_s[k]    = ssq;
        invden_s[k] = iv;
        halfnn_s[k] = 0.5f * ssq * iv * iv;
        gV_s[k]     = g;
    }
    __syncthreads();

    const int q = t;
    float sk[KW], gu[KW];
    #pragma unroll
    for (int k = 0; k < KW; k++) gu[k] = 0.f;
    if (q < NQ) {
        #pragma unroll
        for (int k = 0; k < KW; k++) sk[k] = G[(NQ + k) * PADG + q];
    }

    // ---- Phase 2: 20 layers in SMEM ----
    for (int it = 0; it < NLAYERS; it++) {
        float u[KW];
        if (q < NQ) {
            float a[KW], m = -1e30f;
            #pragma unroll
            for (int k = 0; k < KW; k++) {
                a[k] = inv_t2 * ((gu[k] + sk[k]) * invden_s[k] - halfnn_s[k] + gV_s[k]);
                m = fmaxf(m, a[k]);
            }
            float ssum = 0.f;
            #pragma unroll
            for (int k = 0; k < KW; k++) { u[k] = __expf(a[k] - m); ssum += u[k]; }
            const float r = 1.0f / ssum;
            #pragma unroll
            for (int k = 0; k < KW; k++) u[k] *= r;

            if (it == NLAYERS - 1) {
                float* o = out + ((size_t)b * NQ + q) * KW;
                #pragma unroll
                for (int k = 0; k < KW; k++) o[k] = u[k];
            } else {
                #pragma unroll
                for (int k = 0; k < KW; k++) U_s[q * PADU + k] = u[k];
            }
        }
        if (it == NLAYERS - 1) break;
        __syncthreads();

        if (q < NQ) {
            float ng0 = 0.f, ng1 = 0.f, ng2 = 0.f, ng3 = 0.f, ng4 = 0.f;
            const float* Grow = &G[q * PADG];
            for (int qp = 0; qp < NQ; qp++) {
                const float gv = Grow[qp];
                const float4 u4 = *(const float4*)&U_s[qp * PADU];
                const float  u5 = U_s[qp * PADU + 4];
                ng0 += gv * u4.x; ng1 += gv * u4.y; ng2 += gv * u4.z;
                ng3 += gv * u4.w; ng4 += gv * u5;
            }
            gu[0] = ng0; gu[1] = ng1; gu[2] = ng2; gu[3] = ng3; gu[4] = ng4;
            GU_s[q * PADU + 0] = ng0; GU_s[q * PADU + 1] = ng1;
            GU_s[q * PADU + 2] = ng2; GU_s[q * PADU + 3] = ng3;
            GU_s[q * PADU + 4] = ng4;
        }
        __syncthreads();

        // per-class reductions: warp w handles classes w and w+4
        for (int k = w; k < KW; k += 4) {
            float usum = 0.f, ups = 0.f, ugu = 0.f;
            for (int qq = lane; qq < NQ; qq += 32) {
                const float uv = U_s[qq * PADU + k];
                usum += uv;
                ups  += uv * G[(NQ + k) * PADG + qq];
                ugu  += uv * GU_s[qq * PADU + k];
            }
            #pragma unroll
            for (int o = 16; o > 0; o >>= 1) {
                usum += __shfl_down_sync(0xffffffffu, usum, o);
                ups  += __shfl_down_sync(0xffffffffu, ups,  o);
                ugu  += __shfl_down_sync(0xffffffffu, ugu,  o);
            }
            if (lane == 0) {
                const float den = usum + cnt_s[k];
                const float iv  = 1.0f / den;
                const float nn  = ugu + 2.f * ups + ssq_s[k];
                invden_s[k] = iv;
                halfnn_s[k] = 0.5f * nn * iv * iv;
                gV_s[k]     = g * (logf(usum / (float)NQ + EPS) + 1.0f);
            }
        }
        __syncthreads();
    }
}

extern "C" void kernel_launch(void* const* d_in, const int* in_sizes, int n_in,
                              void* d_out, int out_size)
{
    const float* Zs = (const float*)d_in[0];
    const int*   Y  = (const int*)  d_in[1];
    const float* Zq = (const float*)d_in[2];
    const float* t1 = (const float*)d_in[3];
    const float* gm = (const float*)d_in[4];
    const float* t2 = (const float*)d_in[5];
    fewshot_kernel<<<NTASK, NTHR>>>(Zs, Y, Zq, t1, gm, t2, (float*)d_out);
}